// round 9
// baseline (speedup 1.0000x reference)
#include <cuda_runtime.h>
#include <math.h>

// Problem constants (fixed by the reference)
#define BATCH 8192
#define NCLS  1000
#define DDIM  4096

#define TILE_D      1024
#define NT_D        (DDIM / TILE_D)       // 4 tiles over D
#define NF_BLOCKS   (NCLS * NT_D)         // 4000 fused blocks
#define CE_BLOCKS   (BATCH / 4)           // 2048 CE blocks (warp-per-row, 4/block)
#define FIRST_FUSED CE_BLOCKS
#define GRID_TOTAL  (CE_BLOCKS + NF_BLOCKS)
#define MEGA_T      128
#define NSLOTS      64

// ---------------------------------------------------------------------------
// Device scratch (no allocations allowed)
// ---------------------------------------------------------------------------
__device__ int    g_offsets[1025];     // exclusive class offsets (bins padded)
__device__ int    g_rows[BATCH];       // row ids grouped by class
__device__ int    g_rank[BATCH];       // per-row rank within its class
__device__ double g_l1_slots[NSLOTS];
__device__ double g_l2_slots[NSLOTS];
__device__ int    g_done = 0;          // arrival ticket (reset by last block)

// ---------------------------------------------------------------------------
// 1) prep: zero slots + histogram(rank) + warp-scan + scatter + totals
// ---------------------------------------------------------------------------
__global__ __launch_bounds__(1024)
void prep_kernel(const int* __restrict__ target, float* __restrict__ total_out) {
    __shared__ int scnt[1024];
    __shared__ int soff[1024];
    __shared__ int swarp[32];
    const int tid  = threadIdx.x;
    const int lane = tid & 31;
    const int wid  = tid >> 5;

    if (tid < NSLOTS) { g_l1_slots[tid] = 0.0; g_l2_slots[tid] = 0.0; }
    scnt[tid] = 0;
    __syncthreads();

    // histogram: atomic return value IS the row's rank within its class
    const int4* t4 = reinterpret_cast<const int4*>(target);
    #pragma unroll
    for (int i = tid; i < BATCH / 4; i += 1024) {
        int4 t = t4[i];
        int b = i * 4;
        g_rank[b]     = atomicAdd(&scnt[t.x], 1);
        g_rank[b + 1] = atomicAdd(&scnt[t.y], 1);
        g_rank[b + 2] = atomicAdd(&scnt[t.z], 1);
        g_rank[b + 3] = atomicAdd(&scnt[t.w], 1);
    }
    __syncthreads();

    const int v = scnt[tid];
    if (tid < NCLS) total_out[tid] = (float)v;

    // exclusive scan: warp inclusive scan + warp-base scan
    int incl = v;
    #pragma unroll
    for (int o = 1; o < 32; o <<= 1) {
        int n = __shfl_up_sync(0xffffffffu, incl, o);
        if (lane >= o) incl += n;
    }
    if (lane == 31) swarp[wid] = incl;
    __syncthreads();
    if (wid == 0) {
        int w = swarp[lane];
        int wi = w;
        #pragma unroll
        for (int o = 1; o < 32; o <<= 1) {
            int n = __shfl_up_sync(0xffffffffu, wi, o);
            if (lane >= o) wi += n;
        }
        swarp[lane] = wi - w;   // exclusive warp base
    }
    __syncthreads();
    const int ex = swarp[wid] + incl - v;
    soff[tid] = ex;
    g_offsets[tid] = ex;
    if (tid == 1023) g_offsets[1024] = BATCH;
    __syncthreads();

    // scatter (no atomics — ranks precomputed by this same thread)
    #pragma unroll
    for (int i = tid; i < BATCH / 4; i += 1024) {
        int4 t = t4[i];
        int b = i * 4;
        g_rows[soff[t.x] + g_rank[b]]     = b;
        g_rows[soff[t.y] + g_rank[b + 1]] = b + 1;
        g_rows[soff[t.z] + g_rank[b + 2]] = b + 2;
        g_rows[soff[t.w] + g_rank[b + 3]] = b + 3;
    }
}

// ---------------------------------------------------------------------------
// Element op: 3 MUFU (EX2, RCP.approx, LG2), ~5 FMA/ALU.
//   e = exp(-|x|); r = 1/(1+e); sig = x>=0 ? r : 1-r
//   bce += max(x,0) - x*y + log(1+e)
// ---------------------------------------------------------------------------
__device__ __forceinline__ void elem_op(float x, float y, float& acc, float& bce) {
    const float e = __expf(-fabsf(x));
    const float u = 1.f + e;
    float r;
    asm("rcp.approx.f32 %0, %1;" : "=f"(r) : "f"(u));
    acc += (x >= 0.f) ? r : (1.f - r);
    bce += fmaxf(x, 0.f) - x * y + __logf(u);
}

__device__ __forceinline__ void acc4(const float4 x4, const float4 y4,
                                     float4& acc, float& bce) {
    elem_op(x4.x, y4.x, acc.x, bce);
    elem_op(x4.y, y4.y, acc.y, bce);
    elem_op(x4.z, y4.z, acc.z, bce);
    elem_op(x4.w, y4.w, acc.w, bce);
}

// ---------------------------------------------------------------------------
// last-block loss reduction (shared by both roles)
// ---------------------------------------------------------------------------
__device__ __forceinline__ void arrive_and_maybe_finalize(int tid, float* out_loss) {
    __shared__ int s_last;
    if (tid == 0) {
        __threadfence();
        s_last = (atomicAdd(&g_done, 1) == GRID_TOTAL - 1);
    }
    __syncthreads();
    if (s_last && tid < 32) {
        __threadfence();
        double s1 = g_l1_slots[tid] + g_l1_slots[tid + 32];
        double s2 = g_l2_slots[tid] + g_l2_slots[tid + 32];
        #pragma unroll
        for (int o = 16; o; o >>= 1) {
            s1 += __shfl_xor_sync(0xffffffffu, s1, o);
            s2 += __shfl_xor_sync(0xffffffffu, s2, o);
        }
        if (tid == 0) {
            double loss1 = s1 / (double)BATCH;
            double loss2 = s2 / ((double)BATCH * (double)DDIM);
            out_loss[0] = (float)(0.5 * loss1 + 0.5 * loss2);
            g_done = 0;   // reset for the next graph replay
        }
    }
}

// ---------------------------------------------------------------------------
// 2) mega kernel: bid < CE_BLOCKS -> CE (warp-per-row, 4 rows/block)
//                 else            -> fused segment-sum+BCE tile (unroll x4)
// ---------------------------------------------------------------------------
__global__ __launch_bounds__(MEGA_T)
void mega_kernel(const float* __restrict__ dense_out,
                 const float* __restrict__ dense_labels,
                 const float* __restrict__ logits,
                 const int*   __restrict__ target,
                 float* __restrict__ out_sum,
                 float* __restrict__ out_loss) {
    const int bid = blockIdx.x;
    const int tid = threadIdx.x;
    __shared__ float sred[MEGA_T / 32];

    if (bid < CE_BLOCKS) {
        // ----- CE role: warp-per-row, 4 rows per block -----
        const int warp = tid >> 5;
        const int lane = tid & 31;
        const int row  = bid * 4 + warp;
        const float4* lrow4 =
            reinterpret_cast<const float4*>(logits + (size_t)row * NCLS);

        float4 v[8];
        #pragma unroll
        for (int k = 0; k < 7; k++) v[k] = lrow4[lane + k * 32];
        const bool has7 = lane < (250 - 7 * 32);   // 26 remaining float4
        v[7] = has7 ? lrow4[lane + 224]
                    : make_float4(-INFINITY, -INFINITY, -INFINITY, -INFINITY);

        float mx = -INFINITY;
        #pragma unroll
        for (int k = 0; k < 8; k++)
            mx = fmaxf(mx, fmaxf(fmaxf(v[k].x, v[k].y), fmaxf(v[k].z, v[k].w)));
        #pragma unroll
        for (int o = 16; o; o >>= 1)
            mx = fmaxf(mx, __shfl_xor_sync(0xffffffffu, mx, o));

        float sum = 0.f;
        #pragma unroll
        for (int k = 0; k < 7; k++)
            sum += __expf(v[k].x - mx) + __expf(v[k].y - mx) +
                   __expf(v[k].z - mx) + __expf(v[k].w - mx);
        if (has7)
            sum += __expf(v[7].x - mx) + __expf(v[7].y - mx) +
                   __expf(v[7].z - mx) + __expf(v[7].w - mx);
        #pragma unroll
        for (int o = 16; o; o >>= 1) sum += __shfl_xor_sync(0xffffffffu, sum, o);

        if (lane == 0) {
            float lse = mx + __logf(sum);
            float lt  = logits[(size_t)row * NCLS + target[row]];
            sred[warp] = lse - lt;
        }
        __syncthreads();
        if (tid == 0) {
            float t = sred[0] + sred[1] + sred[2] + sred[3];
            atomicAdd(&g_l1_slots[bid & (NSLOTS - 1)], (double)t);
        }

    } else {
        // ----- fused role: class c, D-tile of 1024 cols, 2 float4/thread ----
        const int fb   = bid - FIRST_FUSED;
        const int c    = fb >> 2;
        const int col0 = ((fb & 3) * TILE_D) + tid * 4;
        const int col1 = col0 + (TILE_D / 2);

        const float4 y0 = *reinterpret_cast<const float4*>(
            dense_labels + (size_t)c * DDIM + col0);
        const float4 y1 = *reinterpret_cast<const float4*>(
            dense_labels + (size_t)c * DDIM + col1);

        float4 acc0 = make_float4(0.f, 0.f, 0.f, 0.f);
        float4 acc1 = make_float4(0.f, 0.f, 0.f, 0.f);
        float bce = 0.f;

        const int s = g_offsets[c];
        const int e = g_offsets[c + 1];

        int i = s;
        // unroll x4: 8 independent float4 loads in flight per thread
        for (; i + 3 < e; i += 4) {
            const float* p0 = dense_out + (size_t)g_rows[i]     * DDIM;
            const float* p1 = dense_out + (size_t)g_rows[i + 1] * DDIM;
            const float* p2 = dense_out + (size_t)g_rows[i + 2] * DDIM;
            const float* p3 = dense_out + (size_t)g_rows[i + 3] * DDIM;
            float4 a[8];
            a[0] = *reinterpret_cast<const float4*>(p0 + col0);
            a[1] = *reinterpret_cast<const float4*>(p0 + col1);
            a[2] = *reinterpret_cast<const float4*>(p1 + col0);
            a[3] = *reinterpret_cast<const float4*>(p1 + col1);
            a[4] = *reinterpret_cast<const float4*>(p2 + col0);
            a[5] = *reinterpret_cast<const float4*>(p2 + col1);
            a[6] = *reinterpret_cast<const float4*>(p3 + col0);
            a[7] = *reinterpret_cast<const float4*>(p3 + col1);
            acc4(a[0], y0, acc0, bce);
            acc4(a[1], y1, acc1, bce);
            acc4(a[2], y0, acc0, bce);
            acc4(a[3], y1, acc1, bce);
            acc4(a[4], y0, acc0, bce);
            acc4(a[5], y1, acc1, bce);
            acc4(a[6], y0, acc0, bce);
            acc4(a[7], y1, acc1, bce);
        }
        for (; i < e; i++) {
            const float* p0 = dense_out + (size_t)g_rows[i] * DDIM;
            const float4 a0 = *reinterpret_cast<const float4*>(p0 + col0);
            const float4 a1 = *reinterpret_cast<const float4*>(p0 + col1);
            acc4(a0, y0, acc0, bce);
            acc4(a1, y1, acc1, bce);
        }

        // scalar stores: out_sum is only 4B-aligned (d_out + 1 float)
        float* dst0 = out_sum + (size_t)c * DDIM + col0;
        dst0[0] = acc0.x; dst0[1] = acc0.y; dst0[2] = acc0.z; dst0[3] = acc0.w;
        float* dst1 = out_sum + (size_t)c * DDIM + col1;
        dst1[0] = acc1.x; dst1[1] = acc1.y; dst1[2] = acc1.z; dst1[3] = acc1.w;

        // block-reduce bce -> one spread double atomic
        #pragma unroll
        for (int o = 16; o; o >>= 1) bce += __shfl_xor_sync(0xffffffffu, bce, o);
        if ((tid & 31) == 0) sred[tid >> 5] = bce;
        __syncthreads();
        if (tid == 0) {
            float t = sred[0] + sred[1] + sred[2] + sred[3];
            atomicAdd(&g_l2_slots[bid & (NSLOTS - 1)], (double)t);
        }
    }

    arrive_and_maybe_finalize(tid, out_loss);
}

// ---------------------------------------------------------------------------
// Launch. Output layout (float32): [loss(1) | dense_output_sum(C*D) | total(C)]
// ---------------------------------------------------------------------------
extern "C" void kernel_launch(void* const* d_in, const int* in_sizes, int n_in,
                              void* d_out, int out_size) {
    const float* logits       = (const float*)d_in[0]; // [B, C]
    const float* dense_out    = (const float*)d_in[1]; // [B, D]
    const int*   target       = (const int*)  d_in[2]; // [B]
    const float* dense_labels = (const float*)d_in[3]; // [C, D]

    float* out       = (float*)d_out;
    float* out_loss  = out;
    float* out_sum   = out + 1;
    float* out_total = out + 1 + (size_t)NCLS * DDIM;

    prep_kernel<<<1, 1024>>>(target, out_total);

    mega_kernel<<<GRID_TOTAL, MEGA_T>>>(dense_out, dense_labels, logits, target,
                                        out_sum, out_loss);
}